// round 15
// baseline (speedup 1.0000x reference)
#include <cuda_runtime.h>
#include <cstdint>

// SigModeOv — converged configuration (best measured: 18.69 us)
//   k_score:    sigmoid(x@W+b), 4 rows/warp, MLP=8, __expf  [this round: 512-thr blocks]
//   k_segments: valley scan -> sentinel-padded starts, warp-shuffle scan
//   k_reduce:   SPB=4 independent 64-thr float4 groups per 256-thr block,
//               predicated up-front loads (MLP=span) for span<=8
#define BB 16
#define LL 2048
#define DD 256
#define MAXSEG 1044   // >= max segments (1025) + SPB sentinel room
#define SPB 4         // segments per reduce block

// ---- scratch (no allocations allowed) ----
__device__ int   g_starts[BB * MAXSEG];   // [0, v1..vk, LL, LL, ...] per row
__device__ float g_dummy_s[BB * LL];      // s sink if layout has no s output
__device__ float g_dummy_len[BB];         // sink if layout has no lengths output

// ============================================================
// Kernel 1: s = sigmoid(x @ W + b)  — 4 rows per warp.
// Block 0 also writes output_lengths (independent of s).
// ============================================================
__global__ void __launch_bounds__(512) k_score(const float* __restrict__ x,
                        const float* __restrict__ W,
                        const float* __restrict__ bias,
                        float* __restrict__ s_out,
                        const int* __restrict__ input_lengths,
                        float* __restrict__ len_out, int M) {
    if (blockIdx.x == 0 && threadIdx.x < BB) {
        float f = ((float)input_lengths[threadIdx.x] / (float)input_lengths[0]) * (float)M;
        len_out[threadIdx.x] = (float)(int)f;
    }

    int gwarp = (blockIdx.x * blockDim.x + threadIdx.x) >> 5;
    int lane  = threadIdx.x & 31;
    int r0 = gwarp * 4;
    if (r0 >= BB * LL) return;

    const float4* wr = reinterpret_cast<const float4*>(W);
    float4 wv0 = __ldg(&wr[lane]);
    float4 wv1 = __ldg(&wr[lane + 32]);

    float4 xv[8];
#pragma unroll
    for (int j = 0; j < 4; j++) {
        const float4* xr = reinterpret_cast<const float4*>(x + (size_t)(r0 + j) * DD);
        xv[2 * j]     = __ldg(&xr[lane]);
        xv[2 * j + 1] = __ldg(&xr[lane + 32]);
    }

    float acc[4];
#pragma unroll
    for (int j = 0; j < 4; j++) {
        float4 a = xv[2 * j], c = xv[2 * j + 1];
        acc[j] = a.x * wv0.x + a.y * wv0.y + a.z * wv0.z + a.w * wv0.w
               + c.x * wv1.x + c.y * wv1.y + c.z * wv1.z + c.w * wv1.w;
    }

#pragma unroll
    for (int off = 16; off; off >>= 1) {
#pragma unroll
        for (int j = 0; j < 4; j++)
            acc[j] += __shfl_xor_sync(0xffffffffu, acc[j], off);
    }

    if (lane == 0) {
        float bv = __ldg(bias);
        float4 sv;
        sv.x = 1.f / (1.f + __expf(-(acc[0] + bv)));
        sv.y = 1.f / (1.f + __expf(-(acc[1] + bv)));
        sv.z = 1.f / (1.f + __expf(-(acc[2] + bv)));
        sv.w = 1.f / (1.f + __expf(-(acc[3] + bv)));
        *reinterpret_cast<float4*>(&s_out[r0]) = sv;
    }
}

// ============================================================
// Kernel 2: valleys -> sentinel-padded starts array
//   starts = [0, v1..vk, LL, LL, ...]; end_m = min(starts[m+1]+2, LL)
// ============================================================
__global__ void k_segments(const float* __restrict__ s_in) {
    __shared__ float sh_s[LL];
    __shared__ int   sh_wtot[8];
    int b    = blockIdx.x;
    int tid  = threadIdx.x;      // 256 threads, 8 warps
    int lane = tid & 31;
    int wid  = tid >> 5;

    for (int m = tid; m < MAXSEG; m += 256) g_starts[b * MAXSEG + m] = LL;
    {
        const float4* src = reinterpret_cast<const float4*>(s_in + (size_t)b * LL);
        float4* dst = reinterpret_cast<float4*>(sh_s);
        for (int i = tid; i < LL / 4; i += 256) dst[i] = __ldg(&src[i]);
    }
    __syncthreads();

    int base = tid * 8;
    int c = 0;
    int lpos[8];
#pragma unroll
    for (int j = 0; j < 8; j++) {
        int l = base + j;
        if (l >= 1 && l <= LL - 2) {
            float sv = sh_s[l];
            if (sv < sh_s[l - 1] && sv < sh_s[l + 1]) lpos[c++] = l;
        }
    }

    int pre = c;
#pragma unroll
    for (int o = 1; o < 32; o <<= 1) {
        int v = __shfl_up_sync(0xffffffffu, pre, o);
        if (lane >= o) pre += v;
    }
    int wtot = __shfl_sync(0xffffffffu, pre, 31);
    int excl = pre - c;
    if (lane == 31) sh_wtot[wid] = wtot;
    __syncthreads();
    int woff = 0;
#pragma unroll
    for (int w = 0; w < 8; w++)
        woff += (w < wid) ? sh_wtot[w] : 0;
    excl += woff;

    for (int i = 0; i < c; i++)
        g_starts[b * MAXSEG + 1 + excl + i] = lpos[i];
    if (tid == 0)
        g_starts[b * MAXSEG + 0] = 0;
}

// ============================================================
// Kernel 3: SPB independent 64-thread groups per 256-thr block.
// Fast path (span<=8): predicated up-front loads — only in-range
// LDGs issue (exact traffic) but all at once (MLP=span).
// ============================================================
__global__ void __launch_bounds__(256) k_reduce(const float* __restrict__ x,
                                                const float* __restrict__ s_in,
                                                float* __restrict__ out,
                                                int M) {
    int b = blockIdx.y;
    int m = blockIdx.x * SPB + (threadIdx.x >> 6);
    int t = threadIdx.x & 63;
    if (m >= M) return;

    int st = __ldg(&g_starts[b * MAXSEG + m]);
    int nx = __ldg(&g_starts[b * MAXSEG + m + 1]);
    int en = min(nx + 2, LL);

    const float4* xb = reinterpret_cast<const float4*>(x + (size_t)b * LL * DD) + t;
    const float*  sb = s_in + (size_t)b * LL;

    float4 num = make_float4(0.f, 0.f, 0.f, 0.f);
    float  den = 0.f;

    if (en - st <= 8) {
        float4 xv[8]; float sv[8];
#pragma unroll
        for (int j = 0; j < 8; j++) {
            if (st + j < en) {
                xv[j] = __ldg(&xb[(size_t)(st + j) * 64]);
                sv[j] = __ldg(&sb[st + j]);
            } else {
                xv[j] = make_float4(0.f, 0.f, 0.f, 0.f);
                sv[j] = 0.f;
            }
        }
#pragma unroll
        for (int j = 0; j < 8; j++) {
            num.x += sv[j] * xv[j].x; num.y += sv[j] * xv[j].y;
            num.z += sv[j] * xv[j].z; num.w += sv[j] * xv[j].w;
            den   += sv[j];
        }
    } else {
        float4 xv; float sv;
        xv = __ldg(&xb[(size_t)st * 64]); sv = __ldg(&sb[st]);
        for (int l = st; l < en; l++) {
            float4 xn; float sn;
            if (l + 1 < en) { xn = __ldg(&xb[(size_t)(l + 1) * 64]); sn = __ldg(&sb[l + 1]); }
            num.x += sv * xv.x; num.y += sv * xv.y;
            num.z += sv * xv.z; num.w += sv * xv.w;
            den   += sv;
            xv = xn; sv = sn;
        }
    }

    float inv = 1.f / fmaxf(den, 1e-6f);
    float4 r = make_float4(num.x * inv, num.y * inv, num.z * inv, num.w * inv);
    reinterpret_cast<float4*>(out + ((size_t)b * M + m) * DD)[t] = r;
}

// ============================================================
extern "C" void kernel_launch(void* const* d_in, const int* in_sizes, int n_in,
                              void* d_out, int out_size) {
    const float* x    = (const float*)d_in[0];
    const float* W    = (const float*)d_in[1];
    const float* bias = (const float*)d_in[2];
    const int*   il   = (const int*)d_in[3];
    float* out = (float*)d_out;

    // Derive M from out_size. Preferred layout: [B*M*D | B lengths | B*L s]
    const long long aux_full = (long long)BB + (long long)BB * LL;
    long long rem = (long long)out_size - aux_full;
    int M;
    float *len_out, *s_out;

    if (rem > 0 && rem % (BB * DD) == 0) {
        M = (int)(rem / (BB * DD));
        len_out = out + (size_t)BB * M * DD;
        s_out   = len_out + BB;
    } else if (out_size % (BB * DD) == 0) {
        M = out_size / (BB * DD);
        float* dl; float* ds;
        cudaGetSymbolAddress((void**)&dl, g_dummy_len);
        cudaGetSymbolAddress((void**)&ds, g_dummy_s);
        len_out = dl; s_out = ds;
    } else {
        M = (out_size - BB) / (BB * DD);
        len_out = out + (size_t)BB * M * DD;
        float* ds;
        cudaGetSymbolAddress((void**)&ds, g_dummy_s);
        s_out = ds;
    }
    if (M < 1) M = 1;

    // Stage 1: scores — 4 rows/warp, 16 warps/block, 512 blocks
    k_score<<<512, 512>>>(x, W, bias, s_out, il, len_out, M);

    // Stage 2: segment extraction
    k_segments<<<BB, 256>>>(s_out);

    // Stage 3: SPB segments per 256-thread block
    int C = (M + SPB - 1) / SPB;
    dim3 grid3(C, BB);
    k_reduce<<<grid3, 256>>>(x, s_out, out, M);
}

// round 16
// speedup vs baseline: 1.1033x; 1.1033x over previous
#include <cuda_runtime.h>
#include <cstdint>

// SigModeOv — FINAL converged configuration (best measured: 18.69 us)
//   k_score:    sigmoid(x@W+b), 4 rows/warp, MLP=8, __expf, 256thr x 1024 blocks
//   k_segments: valley scan -> sentinel-padded starts, warp-shuffle scan
//   k_reduce:   SPB=4 independent 64-thr float4 groups per 256-thr block,
//               predicated up-front loads (MLP=span) for span<=8
#define BB 16
#define LL 2048
#define DD 256
#define MAXSEG 1044   // >= max segments (1025) + SPB sentinel room
#define SPB 4         // segments per reduce block

// ---- scratch (no allocations allowed) ----
__device__ int   g_starts[BB * MAXSEG];   // [0, v1..vk, LL, LL, ...] per row
__device__ float g_dummy_s[BB * LL];      // s sink if layout has no s output
__device__ float g_dummy_len[BB];         // sink if layout has no lengths output

// ============================================================
// Kernel 1: s = sigmoid(x @ W + b)  — 4 rows per warp.
// Block 0 also writes output_lengths (independent of s).
// ============================================================
__global__ void k_score(const float* __restrict__ x,
                        const float* __restrict__ W,
                        const float* __restrict__ bias,
                        float* __restrict__ s_out,
                        const int* __restrict__ input_lengths,
                        float* __restrict__ len_out, int M) {
    if (blockIdx.x == 0 && threadIdx.x < BB) {
        float f = ((float)input_lengths[threadIdx.x] / (float)input_lengths[0]) * (float)M;
        len_out[threadIdx.x] = (float)(int)f;
    }

    int gwarp = (blockIdx.x * blockDim.x + threadIdx.x) >> 5;
    int lane  = threadIdx.x & 31;
    int r0 = gwarp * 4;
    if (r0 >= BB * LL) return;

    const float4* wr = reinterpret_cast<const float4*>(W);
    float4 wv0 = __ldg(&wr[lane]);
    float4 wv1 = __ldg(&wr[lane + 32]);

    float4 xv[8];
#pragma unroll
    for (int j = 0; j < 4; j++) {
        const float4* xr = reinterpret_cast<const float4*>(x + (size_t)(r0 + j) * DD);
        xv[2 * j]     = __ldg(&xr[lane]);
        xv[2 * j + 1] = __ldg(&xr[lane + 32]);
    }

    float acc[4];
#pragma unroll
    for (int j = 0; j < 4; j++) {
        float4 a = xv[2 * j], c = xv[2 * j + 1];
        acc[j] = a.x * wv0.x + a.y * wv0.y + a.z * wv0.z + a.w * wv0.w
               + c.x * wv1.x + c.y * wv1.y + c.z * wv1.z + c.w * wv1.w;
    }

#pragma unroll
    for (int off = 16; off; off >>= 1) {
#pragma unroll
        for (int j = 0; j < 4; j++)
            acc[j] += __shfl_xor_sync(0xffffffffu, acc[j], off);
    }

    if (lane == 0) {
        float bv = __ldg(bias);
        float4 sv;
        sv.x = 1.f / (1.f + __expf(-(acc[0] + bv)));
        sv.y = 1.f / (1.f + __expf(-(acc[1] + bv)));
        sv.z = 1.f / (1.f + __expf(-(acc[2] + bv)));
        sv.w = 1.f / (1.f + __expf(-(acc[3] + bv)));
        *reinterpret_cast<float4*>(&s_out[r0]) = sv;
    }
}

// ============================================================
// Kernel 2: valleys -> sentinel-padded starts array
//   starts = [0, v1..vk, LL, LL, ...]; end_m = min(starts[m+1]+2, LL)
// ============================================================
__global__ void k_segments(const float* __restrict__ s_in) {
    __shared__ float sh_s[LL];
    __shared__ int   sh_wtot[8];
    int b    = blockIdx.x;
    int tid  = threadIdx.x;      // 256 threads, 8 warps
    int lane = tid & 31;
    int wid  = tid >> 5;

    for (int m = tid; m < MAXSEG; m += 256) g_starts[b * MAXSEG + m] = LL;
    {
        const float4* src = reinterpret_cast<const float4*>(s_in + (size_t)b * LL);
        float4* dst = reinterpret_cast<float4*>(sh_s);
        for (int i = tid; i < LL / 4; i += 256) dst[i] = __ldg(&src[i]);
    }
    __syncthreads();

    int base = tid * 8;
    int c = 0;
    int lpos[8];
#pragma unroll
    for (int j = 0; j < 8; j++) {
        int l = base + j;
        if (l >= 1 && l <= LL - 2) {
            float sv = sh_s[l];
            if (sv < sh_s[l - 1] && sv < sh_s[l + 1]) lpos[c++] = l;
        }
    }

    int pre = c;
#pragma unroll
    for (int o = 1; o < 32; o <<= 1) {
        int v = __shfl_up_sync(0xffffffffu, pre, o);
        if (lane >= o) pre += v;
    }
    int wtot = __shfl_sync(0xffffffffu, pre, 31);
    int excl = pre - c;
    if (lane == 31) sh_wtot[wid] = wtot;
    __syncthreads();
    int woff = 0;
#pragma unroll
    for (int w = 0; w < 8; w++)
        woff += (w < wid) ? sh_wtot[w] : 0;
    excl += woff;

    for (int i = 0; i < c; i++)
        g_starts[b * MAXSEG + 1 + excl + i] = lpos[i];
    if (tid == 0)
        g_starts[b * MAXSEG + 0] = 0;
}

// ============================================================
// Kernel 3: SPB independent 64-thread groups per 256-thr block.
// Fast path (span<=8): predicated up-front loads — only in-range
// LDGs issue (exact traffic) but all at once (MLP=span).
// ============================================================
__global__ void __launch_bounds__(256) k_reduce(const float* __restrict__ x,
                                                const float* __restrict__ s_in,
                                                float* __restrict__ out,
                                                int M) {
    int b = blockIdx.y;
    int m = blockIdx.x * SPB + (threadIdx.x >> 6);
    int t = threadIdx.x & 63;
    if (m >= M) return;

    int st = __ldg(&g_starts[b * MAXSEG + m]);
    int nx = __ldg(&g_starts[b * MAXSEG + m + 1]);
    int en = min(nx + 2, LL);

    const float4* xb = reinterpret_cast<const float4*>(x + (size_t)b * LL * DD) + t;
    const float*  sb = s_in + (size_t)b * LL;

    float4 num = make_float4(0.f, 0.f, 0.f, 0.f);
    float  den = 0.f;

    if (en - st <= 8) {
        float4 xv[8]; float sv[8];
#pragma unroll
        for (int j = 0; j < 8; j++) {
            if (st + j < en) {
                xv[j] = __ldg(&xb[(size_t)(st + j) * 64]);
                sv[j] = __ldg(&sb[st + j]);
            } else {
                xv[j] = make_float4(0.f, 0.f, 0.f, 0.f);
                sv[j] = 0.f;
            }
        }
#pragma unroll
        for (int j = 0; j < 8; j++) {
            num.x += sv[j] * xv[j].x; num.y += sv[j] * xv[j].y;
            num.z += sv[j] * xv[j].z; num.w += sv[j] * xv[j].w;
            den   += sv[j];
        }
    } else {
        float4 xv; float sv;
        xv = __ldg(&xb[(size_t)st * 64]); sv = __ldg(&sb[st]);
        for (int l = st; l < en; l++) {
            float4 xn; float sn;
            if (l + 1 < en) { xn = __ldg(&xb[(size_t)(l + 1) * 64]); sn = __ldg(&sb[l + 1]); }
            num.x += sv * xv.x; num.y += sv * xv.y;
            num.z += sv * xv.z; num.w += sv * xv.w;
            den   += sv;
            xv = xn; sv = sn;
        }
    }

    float inv = 1.f / fmaxf(den, 1e-6f);
    float4 r = make_float4(num.x * inv, num.y * inv, num.z * inv, num.w * inv);
    reinterpret_cast<float4*>(out + ((size_t)b * M + m) * DD)[t] = r;
}

// ============================================================
extern "C" void kernel_launch(void* const* d_in, const int* in_sizes, int n_in,
                              void* d_out, int out_size) {
    const float* x    = (const float*)d_in[0];
    const float* W    = (const float*)d_in[1];
    const float* bias = (const float*)d_in[2];
    const int*   il   = (const int*)d_in[3];
    float* out = (float*)d_out;

    // Derive M from out_size. Preferred layout: [B*M*D | B lengths | B*L s]
    const long long aux_full = (long long)BB + (long long)BB * LL;
    long long rem = (long long)out_size - aux_full;
    int M;
    float *len_out, *s_out;

    if (rem > 0 && rem % (BB * DD) == 0) {
        M = (int)(rem / (BB * DD));
        len_out = out + (size_t)BB * M * DD;
        s_out   = len_out + BB;
    } else if (out_size % (BB * DD) == 0) {
        M = out_size / (BB * DD);
        float* dl; float* ds;
        cudaGetSymbolAddress((void**)&dl, g_dummy_len);
        cudaGetSymbolAddress((void**)&ds, g_dummy_s);
        len_out = dl; s_out = ds;
    } else {
        M = (out_size - BB) / (BB * DD);
        len_out = out + (size_t)BB * M * DD;
        float* ds;
        cudaGetSymbolAddress((void**)&ds, g_dummy_s);
        s_out = ds;
    }
    if (M < 1) M = 1;

    // Stage 1: scores — 4 rows/warp, 8 warps/block, 1024 blocks
    k_score<<<1024, 256>>>(x, W, bias, s_out, il, len_out, M);

    // Stage 2: segment extraction
    k_segments<<<BB, 256>>>(s_out);

    // Stage 3: SPB segments per 256-thread block
    int C = (M + SPB - 1) / SPB;
    dim3 grid3(C, BB);
    k_reduce<<<grid3, 256>>>(x, s_out, out, M);
}

// round 17
// speedup vs baseline: 1.1090x; 1.0052x over previous
#include <cuda_runtime.h>
#include <cstdint>

// SigModeOv — converged configuration (best measured: 18.59 us)
//   k_score:    sigmoid(x@W+b), 4 rows/warp, MLP=8, __expf, 256thr x 1024 blocks
//   k_segments: valley scan -> sentinel-padded starts [this round: 512 threads/row]
//   k_reduce:   SPB=4 independent 64-thr float4 groups per 256-thr block,
//               predicated up-front loads (MLP=span) for span<=8
#define BB 16
#define LL 2048
#define DD 256
#define MAXSEG 1044   // >= max segments (1025) + SPB sentinel room
#define SPB 4         // segments per reduce block

// ---- scratch (no allocations allowed) ----
__device__ int   g_starts[BB * MAXSEG];   // [0, v1..vk, LL, LL, ...] per row
__device__ float g_dummy_s[BB * LL];      // s sink if layout has no s output
__device__ float g_dummy_len[BB];         // sink if layout has no lengths output

// ============================================================
// Kernel 1: s = sigmoid(x @ W + b)  — 4 rows per warp.
// Block 0 also writes output_lengths (independent of s).
// ============================================================
__global__ void k_score(const float* __restrict__ x,
                        const float* __restrict__ W,
                        const float* __restrict__ bias,
                        float* __restrict__ s_out,
                        const int* __restrict__ input_lengths,
                        float* __restrict__ len_out, int M) {
    if (blockIdx.x == 0 && threadIdx.x < BB) {
        float f = ((float)input_lengths[threadIdx.x] / (float)input_lengths[0]) * (float)M;
        len_out[threadIdx.x] = (float)(int)f;
    }

    int gwarp = (blockIdx.x * blockDim.x + threadIdx.x) >> 5;
    int lane  = threadIdx.x & 31;
    int r0 = gwarp * 4;
    if (r0 >= BB * LL) return;

    const float4* wr = reinterpret_cast<const float4*>(W);
    float4 wv0 = __ldg(&wr[lane]);
    float4 wv1 = __ldg(&wr[lane + 32]);

    float4 xv[8];
#pragma unroll
    for (int j = 0; j < 4; j++) {
        const float4* xr = reinterpret_cast<const float4*>(x + (size_t)(r0 + j) * DD);
        xv[2 * j]     = __ldg(&xr[lane]);
        xv[2 * j + 1] = __ldg(&xr[lane + 32]);
    }

    float acc[4];
#pragma unroll
    for (int j = 0; j < 4; j++) {
        float4 a = xv[2 * j], c = xv[2 * j + 1];
        acc[j] = a.x * wv0.x + a.y * wv0.y + a.z * wv0.z + a.w * wv0.w
               + c.x * wv1.x + c.y * wv1.y + c.z * wv1.z + c.w * wv1.w;
    }

#pragma unroll
    for (int off = 16; off; off >>= 1) {
#pragma unroll
        for (int j = 0; j < 4; j++)
            acc[j] += __shfl_xor_sync(0xffffffffu, acc[j], off);
    }

    if (lane == 0) {
        float bv = __ldg(bias);
        float4 sv;
        sv.x = 1.f / (1.f + __expf(-(acc[0] + bv)));
        sv.y = 1.f / (1.f + __expf(-(acc[1] + bv)));
        sv.z = 1.f / (1.f + __expf(-(acc[2] + bv)));
        sv.w = 1.f / (1.f + __expf(-(acc[3] + bv)));
        *reinterpret_cast<float4*>(&s_out[r0]) = sv;
    }
}

// ============================================================
// Kernel 2: valleys -> sentinel-padded starts array.
// 512 threads/row: 4 positions per thread, 16-warp shuffle scan.
// ============================================================
__global__ void __launch_bounds__(512) k_segments(const float* __restrict__ s_in) {
    __shared__ float sh_s[LL];
    __shared__ int   sh_wtot[16];
    int b    = blockIdx.x;
    int tid  = threadIdx.x;      // 512 threads, 16 warps
    int lane = tid & 31;
    int wid  = tid >> 5;

    for (int m = tid; m < MAXSEG; m += 512) g_starts[b * MAXSEG + m] = LL;
    {
        const float4* src = reinterpret_cast<const float4*>(s_in + (size_t)b * LL);
        float4* dst = reinterpret_cast<float4*>(sh_s);
        for (int i = tid; i < LL / 4; i += 512) dst[i] = __ldg(&src[i]);
    }
    __syncthreads();

    // each thread owns 4 consecutive positions
    int base = tid * 4;
    int c = 0;
    int lpos[4];
#pragma unroll
    for (int j = 0; j < 4; j++) {
        int l = base + j;
        if (l >= 1 && l <= LL - 2) {
            float sv = sh_s[l];
            if (sv < sh_s[l - 1] && sv < sh_s[l + 1]) lpos[c++] = l;
        }
    }

    int pre = c;
#pragma unroll
    for (int o = 1; o < 32; o <<= 1) {
        int v = __shfl_up_sync(0xffffffffu, pre, o);
        if (lane >= o) pre += v;
    }
    int wtot = __shfl_sync(0xffffffffu, pre, 31);
    int excl = pre - c;
    if (lane == 31) sh_wtot[wid] = wtot;
    __syncthreads();
    int woff = 0;
#pragma unroll
    for (int w = 0; w < 16; w++)
        woff += (w < wid) ? sh_wtot[w] : 0;
    excl += woff;

    for (int i = 0; i < c; i++)
        g_starts[b * MAXSEG + 1 + excl + i] = lpos[i];
    if (tid == 0)
        g_starts[b * MAXSEG + 0] = 0;
}

// ============================================================
// Kernel 3: SPB independent 64-thread groups per 256-thr block.
// Fast path (span<=8): predicated up-front loads — only in-range
// LDGs issue (exact traffic) but all at once (MLP=span).
// ============================================================
__global__ void __launch_bounds__(256) k_reduce(const float* __restrict__ x,
                                                const float* __restrict__ s_in,
                                                float* __restrict__ out,
                                                int M) {
    int b = blockIdx.y;
    int m = blockIdx.x * SPB + (threadIdx.x >> 6);
    int t = threadIdx.x & 63;
    if (m >= M) return;

    int st = __ldg(&g_starts[b * MAXSEG + m]);
    int nx = __ldg(&g_starts[b * MAXSEG + m + 1]);
    int en = min(nx + 2, LL);

    const float4* xb = reinterpret_cast<const float4*>(x + (size_t)b * LL * DD) + t;
    const float*  sb = s_in + (size_t)b * LL;

    float4 num = make_float4(0.f, 0.f, 0.f, 0.f);
    float  den = 0.f;

    if (en - st <= 8) {
        float4 xv[8]; float sv[8];
#pragma unroll
        for (int j = 0; j < 8; j++) {
            if (st + j < en) {
                xv[j] = __ldg(&xb[(size_t)(st + j) * 64]);
                sv[j] = __ldg(&sb[st + j]);
            } else {
                xv[j] = make_float4(0.f, 0.f, 0.f, 0.f);
                sv[j] = 0.f;
            }
        }
#pragma unroll
        for (int j = 0; j < 8; j++) {
            num.x += sv[j] * xv[j].x; num.y += sv[j] * xv[j].y;
            num.z += sv[j] * xv[j].z; num.w += sv[j] * xv[j].w;
            den   += sv[j];
        }
    } else {
        float4 xv; float sv;
        xv = __ldg(&xb[(size_t)st * 64]); sv = __ldg(&sb[st]);
        for (int l = st; l < en; l++) {
            float4 xn; float sn;
            if (l + 1 < en) { xn = __ldg(&xb[(size_t)(l + 1) * 64]); sn = __ldg(&sb[l + 1]); }
            num.x += sv * xv.x; num.y += sv * xv.y;
            num.z += sv * xv.z; num.w += sv * xv.w;
            den   += sv;
            xv = xn; sv = sn;
        }
    }

    float inv = 1.f / fmaxf(den, 1e-6f);
    float4 r = make_float4(num.x * inv, num.y * inv, num.z * inv, num.w * inv);
    reinterpret_cast<float4*>(out + ((size_t)b * M + m) * DD)[t] = r;
}

// ============================================================
extern "C" void kernel_launch(void* const* d_in, const int* in_sizes, int n_in,
                              void* d_out, int out_size) {
    const float* x    = (const float*)d_in[0];
    const float* W    = (const float*)d_in[1];
    const float* bias = (const float*)d_in[2];
    const int*   il   = (const int*)d_in[3];
    float* out = (float*)d_out;

    // Derive M from out_size. Preferred layout: [B*M*D | B lengths | B*L s]
    const long long aux_full = (long long)BB + (long long)BB * LL;
    long long rem = (long long)out_size - aux_full;
    int M;
    float *len_out, *s_out;

    if (rem > 0 && rem % (BB * DD) == 0) {
        M = (int)(rem / (BB * DD));
        len_out = out + (size_t)BB * M * DD;
        s_out   = len_out + BB;
    } else if (out_size % (BB * DD) == 0) {
        M = out_size / (BB * DD);
        float* dl; float* ds;
        cudaGetSymbolAddress((void**)&dl, g_dummy_len);
        cudaGetSymbolAddress((void**)&ds, g_dummy_s);
        len_out = dl; s_out = ds;
    } else {
        M = (out_size - BB) / (BB * DD);
        len_out = out + (size_t)BB * M * DD;
        float* ds;
        cudaGetSymbolAddress((void**)&ds, g_dummy_s);
        s_out = ds;
    }
    if (M < 1) M = 1;

    // Stage 1: scores — 4 rows/warp, 8 warps/block, 1024 blocks
    k_score<<<1024, 256>>>(x, W, bias, s_out, il, len_out, M);

    // Stage 2: segment extraction — 512 threads per batch row
    k_segments<<<BB, 512>>>(s_out);

    // Stage 3: SPB segments per 256-thread block
    int C = (M + SPB - 1) / SPB;
    dim3 grid3(C, BB);
    k_reduce<<<grid3, 256>>>(x, s_out, out, M);
}